// round 4
// baseline (speedup 1.0000x reference)
#include <cuda_runtime.h>
#include <cuda_bf16.h>
#include <cstdint>

#define DDIM 50
#define MAXK 2048
#define TM   128      // rows per CTA
#define TKT  64       // K-slots per tile (double-buffered)
#define PK   72       // smem pitch in bf16 (144B: bank-conflict-free fragments)

// ---------------- static device scratch (pre-split M, two layouts) -----------
__device__ __align__(16) __nv_bfloat16 gMkA[MAXK * 64];   // [slot][d] hi
__device__ __align__(16) __nv_bfloat16 gMkB[MAXK * 64];   // [slot][d] lo
__device__ __align__(16) __nv_bfloat16 gMdA[64 * MAXK];   // [d][slot] hi
__device__ __align__(16) __nv_bfloat16 gMdB[64 * MAXK];   // [d][slot] lo

// ---------------- smem layout (bytes) ----------------------------------------
// Two tile buffers of 4 arrays (KH,KL,DH,DL), each 64*144 = 9216 B.
// X staging (XH 18432 + XL 18432 = 36864) overlays buffer 0 (dead after prologue).
#define ARR   9216
#define BUF   (4 * ARR)                 // 36864
#define SM_TOTAL (2 * BUF)              // 73728
#define OFF_KH 0
#define OFF_KL ARR
#define OFF_DH (2 * ARR)
#define OFF_DL (3 * ARR)
#define SM_XH 0
#define SM_XL (TM * PK * 2)             // 18432

// ---------------- helpers ----------------------------------------------------
__device__ __forceinline__ uint32_t smem_u32(const void* p) {
    uint32_t a;
    asm("{ .reg .u64 t; cvta.to.shared.u64 t, %1; cvt.u32.u64 %0, t; }" : "=r"(a) : "l"(p));
    return a;
}
__device__ __forceinline__ void sts32(uint32_t addr, uint32_t v) {
    asm volatile("st.shared.b32 [%0], %1;" :: "r"(addr), "r"(v) : "memory");
}
__device__ __forceinline__ uint32_t lds32(uint32_t addr) {
    uint32_t v;
    asm("ld.shared.b32 %0, [%1];" : "=r"(v) : "r"(addr));
    return v;
}
__device__ __forceinline__ uint32_t pack2(float lo, float hi) {   // -> bf16x2
    uint32_t r;
    asm("{ .reg .b16 l, h; cvt.rn.bf16.f32 l, %1; cvt.rn.bf16.f32 h, %2; mov.b32 %0, {l, h}; }"
        : "=r"(r) : "f"(lo), "f"(hi));
    return r;
}
__device__ __forceinline__ float bf16_rt(float v) {               // round-trip
    float r;
    asm("{ .reg .b16 t; cvt.rn.bf16.f32 t, %1; cvt.f32.bf16 %0, t; }" : "=f"(r) : "f"(v));
    return r;
}
// D += A * B   (m16n8k16, row.col, bf16 in, f32 accum)
__device__ __forceinline__ void mma(float* d, const uint32_t* a, uint32_t b0, uint32_t b1) {
    asm volatile(
        "mma.sync.aligned.m16n8k16.row.col.f32.bf16.bf16.f32 "
        "{%0,%1,%2,%3}, {%4,%5,%6,%7}, {%8,%9}, {%0,%1,%2,%3};"
        : "+f"(d[0]), "+f"(d[1]), "+f"(d[2]), "+f"(d[3])
        : "r"(a[0]), "r"(a[1]), "r"(a[2]), "r"(a[3]), "r"(b0), "r"(b1));
}
#define CP16(dst, src) asm volatile("cp.async.cg.shared.global [%0], [%1], 16;" :: "r"(dst), "l"(src))
#define CPCOMMIT()     asm volatile("cp.async.commit_group;" ::: "memory")
#define CPWAIT0()      asm volatile("cp.async.wait_group 0;" ::: "memory")

// ---------------- prep: split M into bf16 hi/lo, two layouts (zero-padded) ----
__global__ void prep_kernel(const float* __restrict__ mem, int K) {
    int i = blockIdx.x * blockDim.x + threadIdx.x;
    if (i >= MAXK * 64) return;
    int k = i >> 6, d = i & 63;
    float v = (d < DDIM && k < K) ? mem[k * DDIM + d] : 0.f;
    float h = bf16_rt(v);
    __nv_bfloat16 hb = __float2bfloat16(h);
    __nv_bfloat16 lb = __float2bfloat16(v - h);
    gMkA[k * 64 + d] = hb;
    gMkB[k * 64 + d] = lb;
    gMdA[d * MAXK + k] = hb;
    gMdB[d * MAXK + k] = lb;
}

// ---------------- tile prefetch (all 4 arrays, one cp.async group) ------------
__device__ __forceinline__ void prefetch_tile(uint32_t sb, int t, int tid) {
    const uint32_t base = sb + (uint32_t)((t & 1) * BUF);
    #pragma unroll
    for (int c = tid; c < 512; c += 256) {
        int r = c >> 3, j = c & 7;                       // r: row/d 0..63, j: 16B chunk
        uint32_t doff = (uint32_t)(r * (PK * 2) + j * 16);
        const char* sKA = (const char*)(gMkA + (size_t)(t * TKT + r) * 64) + j * 16;
        const char* sKB = (const char*)(gMkB + (size_t)(t * TKT + r) * 64) + j * 16;
        const char* sDA = (const char*)(gMdA + (size_t)r * MAXK + t * TKT) + j * 16;
        const char* sDB = (const char*)(gMdB + (size_t)r * MAXK + t * TKT) + j * 16;
        CP16(base + OFF_KH + doff, sKA);
        CP16(base + OFF_KL + doff, sKB);
        CP16(base + OFF_DH + doff, sDA);
        CP16(base + OFF_DL + doff, sDB);
    }
    CPCOMMIT();
}

// ---------------- main fused kernel ------------------------------------------
__global__ __launch_bounds__(256, 2)
void memread_mma_kernel(const float* __restrict__ x, float* __restrict__ out, int B, int K) {
    extern __shared__ char smem[];
    const uint32_t sb = smem_u32(smem);
    const int tid = threadIdx.x, wid = tid >> 5, lane = tid & 31;
    const int g = lane >> 2, tg = lane & 3;
    const int row0 = blockIdx.x * TM;

    // ---- prologue: X load, passthrough, hi/lo split into (overlaid) smem ----
    for (int w = tid; w < TM * 32; w += 256) {
        int r = w >> 5, dp = w & 31;
        int row = row0 + r;
        float2 v = make_float2(0.f, 0.f);
        if (dp < 25 && row < B) {
            v = *reinterpret_cast<const float2*>(x + (size_t)row * DDIM + dp * 2);
            *reinterpret_cast<float2*>(out + (size_t)row * 100 + dp * 2) = v;
        }
        float hx = bf16_rt(v.x), hy = bf16_rt(v.y);
        uint32_t off = (uint32_t)(r * (PK * 2) + dp * 4);
        sts32(sb + SM_XH + off, pack2(hx, hy));
        sts32(sb + SM_XL + off, pack2(v.x - hx, v.y - hy));
    }
    __syncthreads();

    // ---- persistent X A-fragments (rows wid*16..+15, k = d = 0..63) ---------
    uint32_t Xh[4][4], Xl[4][4];
    {
        uint32_t base = (uint32_t)((wid * 16 + g) * (PK * 2) + tg * 4);
        #pragma unroll
        for (int ks = 0; ks < 4; ++ks) {
            uint32_t o = base + ks * 32;
            Xh[ks][0] = lds32(sb + SM_XH + o);
            Xh[ks][1] = lds32(sb + SM_XH + o + 8 * PK * 2);
            Xh[ks][2] = lds32(sb + SM_XH + o + 16);
            Xh[ks][3] = lds32(sb + SM_XH + o + 8 * PK * 2 + 16);
            Xl[ks][0] = lds32(sb + SM_XL + o);
            Xl[ks][1] = lds32(sb + SM_XL + o + 8 * PK * 2);
            Xl[ks][2] = lds32(sb + SM_XL + o + 16);
            Xl[ks][3] = lds32(sb + SM_XL + o + 8 * PK * 2 + 16);
        }
    }
    __syncthreads();                      // X smem dead -> becomes tile buffer 0

    float U[7][4];
    #pragma unroll
    for (int nb = 0; nb < 7; ++nb)
        #pragma unroll
        for (int q = 0; q < 4; ++q) U[nb][q] = 0.f;

    const int ntiles = (K + TKT - 1) / TKT;
    prefetch_tile(sb, 0, tid);

    for (int t = 0; t < ntiles; ++t) {
        CPWAIT0();                        // tile t landed
        __syncthreads();
        if (t + 1 < ntiles) prefetch_tile(sb, t + 1, tid);   // overlap with compute

        const uint32_t base = sb + (uint32_t)((t & 1) * BUF);
        const uint32_t KH = base + OFF_KH, KL = base + OFF_KL;
        const uint32_t DH = base + OFF_DH, DL = base + OFF_DL;

        // ---- 4 sub-steps: 2 score blocks -> exp -> GEMM2 k-step -------------
        #pragma unroll 1
        for (int s = 0; s < 4; ++s) {
            float C0m[4] = {0, 0, 0, 0}, C0c[4] = {0, 0, 0, 0};
            float C1m[4] = {0, 0, 0, 0}, C1c[4] = {0, 0, 0, 0};
            uint32_t kb = (uint32_t)(((2 * s) * 8 + g) * (PK * 2) + tg * 4);
            #pragma unroll
            for (int ks = 0; ks < 4; ++ks) {
                uint32_t o = kb + ks * 32;
                uint32_t bh0 = lds32(KH + o);
                uint32_t bh1 = lds32(KH + o + 16);
                uint32_t bl0 = lds32(KL + o);
                uint32_t bl1 = lds32(KL + o + 16);
                mma(C0m, Xh[ks], bh0, bh1);
                mma(C0c, Xh[ks], bl0, bl1);
                mma(C0c, Xl[ks], bh0, bh1);
                uint32_t o1 = o + 8 * (PK * 2);
                uint32_t ch0 = lds32(KH + o1);
                uint32_t ch1 = lds32(KH + o1 + 16);
                uint32_t cl0 = lds32(KL + o1);
                uint32_t cl1 = lds32(KL + o1 + 16);
                mma(C1m, Xh[ks], ch0, ch1);
                mma(C1c, Xh[ks], cl0, cl1);
                mma(C1c, Xl[ks], ch0, ch1);
            }
            // exp + split + pack into GEMM2 A-fragments (register-only S)
            float e0 = __expf(C0m[0] + C0c[0]);
            float e1 = __expf(C0m[1] + C0c[1]);
            float e2 = __expf(C0m[2] + C0c[2]);
            float e3 = __expf(C0m[3] + C0c[3]);
            float e4 = __expf(C1m[0] + C1c[0]);
            float e5 = __expf(C1m[1] + C1c[1]);
            float e6 = __expf(C1m[2] + C1c[2]);
            float e7 = __expf(C1m[3] + C1c[3]);
            float h0 = bf16_rt(e0), h1 = bf16_rt(e1), h2 = bf16_rt(e2), h3 = bf16_rt(e3);
            float h4 = bf16_rt(e4), h5 = bf16_rt(e5), h6 = bf16_rt(e6), h7 = bf16_rt(e7);
            uint32_t ah[4], al[4];
            ah[0] = pack2(h0, h1);  ah[1] = pack2(h2, h3);
            ah[2] = pack2(h4, h5);  ah[3] = pack2(h6, h7);
            al[0] = pack2(e0 - h0, e1 - h1);  al[1] = pack2(e2 - h2, e3 - h3);
            al[2] = pack2(e4 - h4, e5 - h5);  al[3] = pack2(e6 - h6, e7 - h7);

            // GEMM2 k-step: U[16 x 56] += S * Md   (7 n-blocks cover D=50)
            uint32_t db = (uint32_t)(g * (PK * 2) + s * 32 + tg * 4);
            #pragma unroll
            for (int nb = 0; nb < 7; ++nb) {
                uint32_t o = db + nb * 8 * (PK * 2);
                uint32_t bh0 = lds32(DH + o);
                uint32_t bh1 = lds32(DH + o + 16);
                uint32_t bl0 = lds32(DL + o);
                uint32_t bl1 = lds32(DL + o + 16);
                mma(U[nb], ah, bh0, bh1);
                mma(U[nb], al, bh0, bh1);
                mma(U[nb], ah, bl0, bl1);
            }
        }
        __syncthreads();                  // all warps done with buffer t&1
    }

    // ---- writeout U -> out[:, 50:100] ---------------------------------------
    const int r1 = row0 + wid * 16 + g;
    const int r2 = r1 + 8;
    #pragma unroll
    for (int nb = 0; nb < 7; ++nb) {
        int col = nb * 8 + tg * 2;
        if (col < DDIM) {
            if (r1 < B)
                *reinterpret_cast<float2*>(out + (size_t)r1 * 100 + 50 + col) =
                    make_float2(U[nb][0], U[nb][1]);
            if (r2 < B)
                *reinterpret_cast<float2*>(out + (size_t)r2 * 100 + 50 + col) =
                    make_float2(U[nb][2], U[nb][3]);
        }
    }
}

// ---------------- launch -----------------------------------------------------
extern "C" void kernel_launch(void* const* d_in, const int* in_sizes, int n_in,
                              void* d_out, int out_size) {
    const float* x   = (const float*)d_in[0];
    const float* mem = (const float*)d_in[1];
    float* out       = (float*)d_out;
    const int B = in_sizes[0] / DDIM;
    const int K = in_sizes[1] / DDIM;

    cudaFuncSetAttribute(memread_mma_kernel,
                         cudaFuncAttributeMaxDynamicSharedMemorySize, SM_TOTAL);

    prep_kernel<<<(MAXK * 64 + 255) / 256, 256>>>(mem, K);

    const int grid = (B + TM - 1) / TM;
    memread_mma_kernel<<<grid, 256, SM_TOTAL>>>(x, out, B, K);
}